// round 1
// baseline (speedup 1.0000x reference)
#include <cuda_runtime.h>
#include <cuda_bf16.h>

typedef unsigned long long ull;

#define Bsz 1024
#define Dd  1024
#define Ff  32768
#define L0  32
#define BM  128
#define BN  128
#define BK  16
#define NT  (Ff/BN)   // 256 column tiles

// ---------------- persistent device scratch (no allocs allowed) ----------------
__device__ float g_resid[Bsz*Dd];        // 4 MB residual
__device__ float g_cand_val[Bsz*NT];     // per (row, col-tile) max IP value
__device__ int   g_cand_idx[Bsz*NT];     // and its atom index
__device__ int   g_nsel[Bsz];            // active-list length per row
__device__ int   g_sel_idx[Bsz*34];      // atoms ever selected (<=32)
__device__ float g_sel_w[Bsz*34];        // their current weights

// ---------------- f32x2 packed-FMA helpers (Blackwell only; ptxas never emits) --
__device__ __forceinline__ void fma2(ull &d, ull a, ull b){
    asm("fma.rn.f32x2 %0, %1, %2, %0;" : "+l"(d) : "l"(a), "l"(b));
}
__device__ __forceinline__ ull pack2(float x, float y){
    ull r; asm("mov.b64 %0, {%1, %2};" : "=l"(r) : "f"(x), "f"(y)); return r;
}
__device__ __forceinline__ void unpack2(ull v, float &lo, float &hi){
    asm("mov.b64 {%0, %1}, %2;" : "=f"(lo), "=f"(hi) : "l"(v));
}

__device__ __forceinline__ float block_sum(float v, float* s){
    const int lane = threadIdx.x & 31, w = threadIdx.x >> 5;
#pragma unroll
    for (int o = 16; o; o >>= 1) v += __shfl_xor_sync(0xffffffffu, v, o);
    __syncthreads();                 // protect s reuse from a previous call
    if (lane == 0) s[w] = v;
    __syncthreads();
    float r = 0.f;
#pragma unroll
    for (int i = 0; i < 8; i++) r += s[i];   // fixed order -> deterministic
    return r;
}

// ---------------- K0: residual = x, empty active lists ----------------
__global__ void itda_init(const float* __restrict__ x){
    const int b = blockIdx.x;
    ((float4*)(g_resid + (size_t)b*Dd))[threadIdx.x] =
        ((const float4*)(x + (size_t)b*Dd))[threadIdx.x];
    if (threadIdx.x == 0) g_nsel[b] = 0;
}

// ---------------- K1: fp32 GEMM (ip = resid @ xs^T) fused with per-tile argmax --
__global__ __launch_bounds__(256)
void itda_gemm(const float* __restrict__ xsm){
    __shared__ __align__(16) float As[2][BK][BM+4];
    __shared__ __align__(16) float Bs[2][BK][BN+4];
    const int tid = threadIdx.x;
    const int bx = blockIdx.x, by = blockIdx.y;   // bx: F tile (256), by: B tile (8)
    const int tx = tid & 15, ty = tid >> 4;
    const int lrow = tid >> 2;            // 0..63
    const int lk   = (tid & 3) << 2;      // 0,4,8,12

    const float* Ag = g_resid + (size_t)(by*BM + lrow)*Dd + lk;
    const float* Bg = xsm     + (size_t)(bx*BN + lrow)*Dd + lk;

    ull acc[8][4];
#pragma unroll
    for (int i = 0; i < 8; i++)
#pragma unroll
        for (int j = 0; j < 4; j++) acc[i][j] = 0ULL;

    float4 a0, a1, b0, b1;
    a0 = *(const float4*)(Ag);
    a1 = *(const float4*)(Ag + 64*Dd);
    b0 = *(const float4*)(Bg);
    b1 = *(const float4*)(Bg + 64*Dd);
    {
        const float av0[4] = {a0.x,a0.y,a0.z,a0.w}, av1[4] = {a1.x,a1.y,a1.z,a1.w};
        const float bv0[4] = {b0.x,b0.y,b0.z,b0.w}, bv1[4] = {b1.x,b1.y,b1.z,b1.w};
#pragma unroll
        for (int q = 0; q < 4; q++){
            As[0][lk+q][lrow] = av0[q]; As[0][lk+q][lrow+64] = av1[q];
            Bs[0][lk+q][lrow] = bv0[q]; Bs[0][lk+q][lrow+64] = bv1[q];
        }
    }
    __syncthreads();

    const int TCH = Dd / BK;  // 64 K-chunks
    for (int t = 0; t < TCH; t++){
        const int cur = t & 1;
        if (t + 1 < TCH){
            const float* Ap = Ag + (t+1)*BK;
            const float* Bp = Bg + (t+1)*BK;
            a0 = *(const float4*)(Ap);
            a1 = *(const float4*)(Ap + 64*Dd);
            b0 = *(const float4*)(Bp);
            b1 = *(const float4*)(Bp + 64*Dd);
        }
#pragma unroll
        for (int k = 0; k < BK; k++){
            const float* ap = &As[cur][k][ty*8];
            const float4 af0 = *(const float4*)(ap);
            const float4 af1 = *(const float4*)(ap+4);
            const ulonglong2* bp = (const ulonglong2*)&Bs[cur][k][tx*8];
            const ulonglong2 bq0 = bp[0];
            const ulonglong2 bq1 = bp[1];
            const float av[8] = {af0.x,af0.y,af0.z,af0.w,af1.x,af1.y,af1.z,af1.w};
#pragma unroll
            for (int i = 0; i < 8; i++){
                const ull aa = pack2(av[i], av[i]);
                fma2(acc[i][0], aa, bq0.x);
                fma2(acc[i][1], aa, bq0.y);
                fma2(acc[i][2], aa, bq1.x);
                fma2(acc[i][3], aa, bq1.y);
            }
        }
        if (t + 1 < TCH){
            const int nxt = cur ^ 1;
            const float av0[4] = {a0.x,a0.y,a0.z,a0.w}, av1[4] = {a1.x,a1.y,a1.z,a1.w};
            const float bv0[4] = {b0.x,b0.y,b0.z,b0.w}, bv1[4] = {b1.x,b1.y,b1.z,b1.w};
#pragma unroll
            for (int q = 0; q < 4; q++){
                As[nxt][lk+q][lrow] = av0[q]; As[nxt][lk+q][lrow+64] = av1[q];
                Bs[nxt][lk+q][lrow] = bv0[q]; Bs[nxt][lk+q][lrow+64] = bv1[q];
            }
            __syncthreads();
        }
    }

    // epilogue: per-row max over this 128-col tile (first-index tie rule)
    const int colbase = bx*BN + tx*8;
#pragma unroll
    for (int i = 0; i < 8; i++){
        float bv = -1e30f; int bi = 0;
#pragma unroll
        for (int j = 0; j < 4; j++){
            float lo, hi; unpack2(acc[i][j], lo, hi);
            const int c0 = colbase + 2*j;
            if (lo > bv){ bv = lo; bi = c0;   }
            if (hi > bv){ bv = hi; bi = c0+1; }
        }
#pragma unroll
        for (int s = 8; s >= 1; s >>= 1){
            const float ov = __shfl_xor_sync(0xffffffffu, bv, s);
            const int   oi = __shfl_xor_sync(0xffffffffu, bi, s);
            if (ov > bv || (ov == bv && oi < bi)){ bv = ov; bi = oi; }
        }
        if (tx == 0){
            const int grow = by*BM + ty*8 + i;
            g_cand_val[grow*NT + bx] = bv;
            g_cand_idx[grow*NT + bx] = bi;
        }
    }
}

// ---------------- K2: per-row argmax (top-8 + exact rescore) + pursuit update ---
__global__ void itda_update(const float* __restrict__ x, const float* __restrict__ xsm){
    const int b = blockIdx.x, tid = threadIdx.x;
    __shared__ float sv[256];
    __shared__ int   si[256];
    __shared__ float sred[8];
    __shared__ int   s_top[8];
    __shared__ int   s_list[34];
    __shared__ float s_w[34];
    __shared__ float s_grad[34];
    __shared__ int   s_n, s_newpos;

    const float4 r4 = ((const float4*)(g_resid + (size_t)b*Dd))[tid];

    // --- top-8 candidates by (exact) tile-max value ---
    float cv = g_cand_val[b*NT + tid];
    int   ci = g_cand_idx[b*NT + tid];
    for (int r = 0; r < 8; r++){
        __syncthreads();
        sv[tid] = cv; si[tid] = ci;
        __syncthreads();
        for (int off = 128; off; off >>= 1){
            if (tid < off){
                const float ov = sv[tid+off]; const int oi = si[tid+off];
                if (ov > sv[tid] || (ov == sv[tid] && oi < si[tid])){ sv[tid]=ov; si[tid]=oi; }
            }
            __syncthreads();
        }
        const int win = si[0];
        if (tid == 0) s_top[r] = win;
        if (ci == win) cv = -1e30f;
    }
    __syncthreads();

    // --- exact fp32 rescore of candidates -> argmax (first-index tie rule) ---
    float best = -1e30f; int bidx = 0x7fffffff;
    for (int r = 0; r < 8; r++){
        const int c = s_top[r];
        const float4 v = ((const float4*)(xsm + (size_t)c*Dd))[tid];
        const float e = block_sum(r4.x*v.x + r4.y*v.y + r4.z*v.z + r4.w*v.w, sred);
        if (e > best || (e == best && c < bidx)){ best = e; bidx = c; }
    }

    // --- active list: S = {w>0} U {argmax} ---
    const int n0 = g_nsel[b];
    if (tid < n0){ s_list[tid] = g_sel_idx[b*34 + tid]; s_w[tid] = g_sel_w[b*34 + tid]; }
    __syncthreads();
    if (tid == 0){
        int pos = -1, n = n0;
        for (int j = 0; j < n; j++) if (s_list[j] == bidx){ pos = j; break; }
        if (pos < 0){ pos = n; s_list[n] = bidx; s_w[n] = 0.f; n++; }
        s_n = n; s_newpos = pos;
    }
    __syncthreads();
    const int n = s_n, newpos = s_newpos;

    // --- grads (exact IPs on S) + c = grad @ xs fused ---
    float4 c4 = make_float4(0.f,0.f,0.f,0.f);
    for (int j = 0; j < n; j++){
        const bool inS = (s_w[j] > 0.f) || (j == newpos);  // uniform across block
        if (inS){
            const float4 v = ((const float4*)(xsm + (size_t)s_list[j]*Dd))[tid];
            const float g = block_sum(r4.x*v.x + r4.y*v.y + r4.z*v.z + r4.w*v.w, sred);
            if (tid == 0) s_grad[j] = g;
            c4.x += g*v.x; c4.y += g*v.y; c4.z += g*v.z; c4.w += g*v.w;
        } else {
            if (tid == 0) s_grad[j] = 0.f;
        }
    }
    const float csq  = block_sum(c4.x*c4.x + c4.y*c4.y + c4.z*c4.z + c4.w*c4.w, sred);
    const float cr   = block_sum(c4.x*r4.x + c4.y*r4.y + c4.z*r4.z + c4.w*r4.w, sred);
    const float step = cr / fmaxf(csq, 1e-3f);

    if (tid == 0){
        for (int j = 0; j < n; j++)
            s_w[j] = fmaxf(0.f, s_w[j] + step * s_grad[j]);   // relu; grad=0 keeps w
    }
    __syncthreads();

    // --- residual = x - sum_j w_j * xs_j (recomputed exactly, no drift) ---
    float4 xv = ((const float4*)(x + (size_t)b*Dd))[tid];
    for (int j = 0; j < n; j++){
        const float w = s_w[j];
        if (w > 0.f){
            const float4 v = ((const float4*)(xsm + (size_t)s_list[j]*Dd))[tid];
            xv.x -= w*v.x; xv.y -= w*v.y; xv.z -= w*v.z; xv.w -= w*v.w;
        }
    }
    ((float4*)(g_resid + (size_t)b*Dd))[tid] = xv;

    if (tid == 0) g_nsel[b] = n;
    if (tid < n){ g_sel_idx[b*34 + tid] = s_list[tid]; g_sel_w[b*34 + tid] = s_w[tid]; }
}

// ---------------- K3: top_k ordering, padding, decode, losses ----------------
__global__ void itda_final(const float* __restrict__ xsm, const float* __restrict__ ysm,
                           const float* __restrict__ y,
                           float* __restrict__ wout, float* __restrict__ iout,
                           float* __restrict__ xr, float* __restrict__ yr,
                           float* __restrict__ ls){
    const int b = blockIdx.x, tid = threadIdx.x;
    __shared__ int   pi[33];
    __shared__ float pw[33];
    __shared__ int   oidx[32];
    __shared__ float ow[32];
    __shared__ int   s_np;
    __shared__ float sred[8];

    if (tid == 0){
        const int nl = g_nsel[b];
        int np = 0;
        for (int j = 0; j < nl; j++){
            const float w = g_sel_w[b*34 + j];
            if (w > 0.f){ pi[np] = g_sel_idx[b*34 + j]; pw[np] = w; np++; }
        }
        // selection sort: descending weight, ascending index on ties (lax.top_k order)
        for (int a = 0; a < np; a++){
            int bst = a;
            for (int c = a+1; c < np; c++)
                if (pw[c] > pw[bst] || (pw[c] == pw[bst] && pi[c] < pi[bst])) bst = c;
            const float tw = pw[a]; pw[a] = pw[bst]; pw[bst] = tw;
            const int   ti = pi[a]; pi[a] = pi[bst]; pi[bst] = ti;
        }
        // padding: zeros with smallest unused indices (lax.top_k tie rule)
        int f = 0;
        for (int k = 0; k < L0; k++){
            if (k < np){ ow[k] = pw[k]; oidx[k] = pi[k]; }
            else {
                for (;;){
                    bool used = false;
                    for (int q = 0; q < np; q++) if (pi[q] == f){ used = true; break; }
                    if (!used) break;
                    f++;
                }
                oidx[k] = f; ow[k] = 0.f; f++;
            }
        }
        s_np = np;
    }
    __syncthreads();

    if (tid < L0){
        wout[b*L0 + tid] = ow[tid];
        iout[b*L0 + tid] = (float)oidx[tid];
    }
    const int np = s_np;

    float4 ax = make_float4(0.f,0.f,0.f,0.f);
    float4 ay = make_float4(0.f,0.f,0.f,0.f);
    for (int k = 0; k < np; k++){
        const float w = ow[k];
        const size_t off = (size_t)oidx[k]*Dd;
        const float4 vx = ((const float4*)(xsm + off))[tid];
        const float4 vy = ((const float4*)(ysm + off))[tid];
        ax.x += w*vx.x; ax.y += w*vx.y; ax.z += w*vx.z; ax.w += w*vx.w;
        ay.x += w*vy.x; ay.y += w*vy.y; ay.z += w*vy.z; ay.w += w*vy.w;
    }
    ((float4*)(xr + (size_t)b*Dd))[tid] = ax;
    ((float4*)(yr + (size_t)b*Dd))[tid] = ay;

    const float4 yv = ((const float4*)(y + (size_t)b*Dd))[tid];
    const float d0 = ay.x - yv.x, d1 = ay.y - yv.y, d2 = ay.z - yv.z, d3 = ay.w - yv.w;
    const float L = block_sum(d0*d0 + d1*d1 + d2*d2 + d3*d3, sred);
    if (tid == 0) ls[b] = L;
}

// ---------------- entry ----------------
extern "C" void kernel_launch(void* const* d_in, const int* in_sizes, int n_in,
                              void* d_out, int out_size){
    const float* x  = (const float*)d_in[0];
    const float* y  = (const float*)d_in[1];
    const float* xs = (const float*)d_in[2];
    const float* ys = (const float*)d_in[3];
    // d_in[4] = target_l0 (32), compiled in

    float* out  = (float*)d_out;
    float* wout = out;                    // [1024, 32]
    float* iout = out + Bsz*L0;           // [1024, 32] (indices as float)
    float* xr   = iout + Bsz*L0;          // [1024, 1024]
    float* yr   = xr + (size_t)Bsz*Dd;    // [1024, 1024]
    float* ls   = yr + (size_t)Bsz*Dd;    // [1024]

    itda_init<<<Bsz, 256>>>(x);
    for (int it = 0; it < L0; it++){
        itda_gemm<<<dim3(NT, Bsz/BM), 256>>>(xs);
        itda_update<<<Bsz, 256>>>(x, xs);
    }
    itda_final<<<Bsz, 256>>>(xs, ys, y, wout, iout, xr, yr, ls);
}

// round 4
// speedup vs baseline: 5.2154x; 5.2154x over previous
#include <cuda_runtime.h>
#include <cuda_bf16.h>
#include <cstdint>

typedef unsigned long long ull;

#define Bsz 1024
#define Dd  1024
#define Ff  32768
#define L0  32
#define BN  128
#define NT  (Ff/BN)        // 256 column tiles
#define KC  64             // K per chunk (one tile image col block)
#define NCH (Dd/KC)        // 16 chunks
#define TILE_B 16384       // 128 rows x 64 bf16 = 16KB
#define NTSEL 10           // tiles selected for rescoring (2 atoms each)

// ---------------- persistent device scratch ----------------
__device__ float g_resid[Bsz*Dd];                       // fp32 residual (exact path)
__device__ __align__(16) ull g_xs_t[(size_t)Ff*Dd/4];   // 64MB: xs bf16, tiled+swizzled
__device__ __align__(16) ull g_a_t[(size_t)Bsz*Dd/4];   // 2MB: residual bf16, tiled+swizzled
__device__ float g_cand_val[Bsz*NT];                    // per-tile best (bf16-approx)
__device__ int   g_cand_idx[Bsz*NT];
__device__ float g_cand_val2[Bsz*NT];                   // per-tile runner-up
__device__ int   g_cand_idx2[Bsz*NT];
__device__ int   g_nsel[Bsz];
__device__ int   g_sel_idx[Bsz*34];
__device__ float g_sel_w[Bsz*34];

// ---------------- helpers ----------------
__device__ __forceinline__ uint32_t smem_u32(const void* p){
    uint32_t a; asm("{ .reg .u64 t; cvta.to.shared.u64 t, %1; cvt.u32.u64 %0, t; }"
                    : "=r"(a) : "l"(p)); return a;
}
__device__ __forceinline__ void cp16(uint32_t dst, const void* src){
    asm volatile("cp.async.cg.shared.global [%0], [%1], 16;" :: "r"(dst), "l"(src) : "memory");
}
__device__ __forceinline__ void cp_commit(){
    asm volatile("cp.async.commit_group;" ::: "memory");
}
__device__ __forceinline__ void cp_wait1(){
    asm volatile("cp.async.wait_group 1;" ::: "memory");
}
__device__ __forceinline__ void cp_wait0(){
    asm volatile("cp.async.wait_group 0;" ::: "memory");
}
__device__ __forceinline__ void ldmx4(uint32_t* r, uint32_t addr){
    asm volatile("ldmatrix.sync.aligned.m8n8.x4.shared.b16 {%0,%1,%2,%3}, [%4];"
        : "=r"(r[0]), "=r"(r[1]), "=r"(r[2]), "=r"(r[3]) : "r"(addr));
}
__device__ __forceinline__ void mma16816(float* d, const uint32_t* a, uint32_t b0, uint32_t b1){
    asm volatile("mma.sync.aligned.m16n8k16.row.col.f32.bf16.bf16.f32 "
        "{%0,%1,%2,%3}, {%4,%5,%6,%7}, {%8,%9}, {%0,%1,%2,%3};"
        : "+f"(d[0]), "+f"(d[1]), "+f"(d[2]), "+f"(d[3])
        : "r"(a[0]), "r"(a[1]), "r"(a[2]), "r"(a[3]), "r"(b0), "r"(b1));
}
__device__ __forceinline__ uint32_t swoff(int row, int colb){
    uint32_t o = (uint32_t)(row*128 + colb);
    return o ^ ((o >> 3) & 0x70);
}
__device__ __forceinline__ ull pack4bf(float a, float b, float c, float d){
    __nv_bfloat162 lo = __floats2bfloat162_rn(a, b);
    __nv_bfloat162 hi = __floats2bfloat162_rn(c, d);
    uint32_t ulo = *reinterpret_cast<uint32_t*>(&lo);
    uint32_t uhi = *reinterpret_cast<uint32_t*>(&hi);
    return (ull)ulo | ((ull)uhi << 32);
}
// store one float4 of residual row b (dims 4*tid..) into tiled bf16 image
__device__ __forceinline__ void store_resid_bf16(int b, int tid, float4 v){
    const int m_tile = b >> 7, row = b & 127;
    const int kc = tid >> 4, cg = tid & 15;
    char* dst = (char*)g_a_t + (size_t)(m_tile*NCH + kc)*TILE_B;
    *(ull*)(dst + swoff(row, cg*8)) = pack4bf(v.x, v.y, v.z, v.w);
}
__device__ __forceinline__ float block_sum(float v, float* s){
    const int lane = threadIdx.x & 31, w = threadIdx.x >> 5;
#pragma unroll
    for (int o = 16; o; o >>= 1) v += __shfl_xor_sync(0xffffffffu, v, o);
    __syncthreads();
    if (lane == 0) s[w] = v;
    __syncthreads();
    float r = 0.f;
#pragma unroll
    for (int i = 0; i < 8; i++) r += s[i];
    return r;
}
__device__ __forceinline__ bool better(float a, int ai, float b, int bi){
    return (a > b) || (a == b && ai < bi);
}
// merge candidate (w,j) into a running top-2
__device__ __forceinline__ void top2_push(float &v1, int &i1, float &v2, int &i2, float w, int j){
    if (better(w, j, v1, i1)){ v2 = v1; i2 = i1; v1 = w; i1 = j; }
    else if (better(w, j, v2, i2)){ v2 = w; i2 = j; }
}

// ---------------- K-1: dictionary -> tiled/swizzled bf16 (once per launch) ----
__global__ void conv_xs(const float* __restrict__ xs){
    const int tile = blockIdx.x;               // n_tile*NCH + kc
    const int n_tile = tile >> 4, kc = tile & 15;
    char* dst = (char*)g_xs_t + (size_t)tile*TILE_B;
    for (int g = threadIdx.x; g < 2048; g += 256){
        const int row = g >> 4, cg = g & 15;
        const float4 v = *(const float4*)(xs + (size_t)(n_tile*128 + row)*Dd + kc*KC + cg*4);
        *(ull*)(dst + swoff(row, cg*8)) = pack4bf(v.x, v.y, v.z, v.w);
    }
}

// ---------------- K0: residual = x ----------------
__global__ void itda_init(const float* __restrict__ x){
    const int b = blockIdx.x;
    const float4 v = ((const float4*)(x + (size_t)b*Dd))[threadIdx.x];
    ((float4*)(g_resid + (size_t)b*Dd))[threadIdx.x] = v;
    store_resid_bf16(b, threadIdx.x, v);
    if (threadIdx.x == 0) g_nsel[b] = 0;
}

// ---------------- K1: bf16 HMMA GEMM + per-tile TOP-2 argmax epilogue ----------------
// CTA: 128(M) x 128(N) x K=1024. 8 warps: warp_m = wid&3 (32 rows), warp_n = wid>>2 (64 cols)
__global__ void __launch_bounds__(256, 2) itda_gemm_mma(){
    extern __shared__ __align__(16) char smem_raw[];
    uint32_t sb = (smem_u32(smem_raw) + 127u) & ~127u;
    const int tid = threadIdx.x, wid = tid >> 5, lane = tid & 31;
    const int mt = blockIdx.x, nt = blockIdx.y;
    const int warp_m = wid & 3, warp_n = wid >> 2;

    const char* gA = (const char*)g_a_t  + (size_t)mt*NCH*TILE_B;
    const char* gB = (const char*)g_xs_t + (size_t)nt*NCH*TILE_B;

    float acc[2][8][4];
#pragma unroll
    for (int i = 0; i < 2; i++)
#pragma unroll
        for (int j = 0; j < 8; j++)
#pragma unroll
            for (int q = 0; q < 4; q++) acc[i][j][q] = 0.f;

    const int lrow = ((lane >> 3) & 1)*8 + (lane & 7);
    const int lkb  = (lane >> 4)*16;
    const int rA0 = warp_m*32 + lrow;
    const int rB0 = warp_n*64 + lrow;

    auto issue = [&](int c, int s){
        const uint32_t dA = sb + s*32768 + tid*16;
        const uint32_t dB = dA + 16384;
        const char* srcA = gA + (size_t)c*TILE_B + tid*16;
        const char* srcB = gB + (size_t)c*TILE_B + tid*16;
#pragma unroll
        for (int i = 0; i < 4; i++){
            cp16(dA + i*4096, srcA + i*4096);
            cp16(dB + i*4096, srcB + i*4096);
        }
        cp_commit();
    };

    issue(0, 0);
    for (int c = 0; c < NCH; c++){
        const int s = c & 1;
        if (c + 1 < NCH){ issue(c+1, s^1); cp_wait1(); }
        else            { cp_wait0(); }
        __syncthreads();
        const uint32_t sA = sb + s*32768;
        const uint32_t sB = sA + 16384;
#pragma unroll
        for (int ks = 0; ks < 4; ks++){
            const int kb = ks*32 + lkb;
            uint32_t a[2][4];
            ldmx4(a[0], sA + swoff(rA0,      kb));
            ldmx4(a[1], sA + swoff(rA0 + 16, kb));
            uint32_t b[4][4];
#pragma unroll
            for (int nb = 0; nb < 4; nb++)
                ldmx4(b[nb], sB + swoff(rB0 + nb*16, kb));
#pragma unroll
            for (int mb = 0; mb < 2; mb++)
#pragma unroll
                for (int n8 = 0; n8 < 8; n8++){
                    const int nb = n8 >> 1, t = n8 & 1;
                    mma16816(acc[mb][n8], a[mb], b[nb][t], b[nb][2+t]);
                }
        }
        __syncthreads();
    }

    // epilogue: per-row TOP-2 (val, first-idx) over this 128-col tile
    float* sval1 = (float*)smem_raw;             // [128][2]
    int*   sidx1 = (int*)(smem_raw + 1024);
    float* sval2 = (float*)(smem_raw + 2048);
    int*   sidx2 = (int*)(smem_raw + 3072);
#pragma unroll
    for (int mb = 0; mb < 2; mb++)
#pragma unroll
        for (int h = 0; h < 2; h++){
            float v1 = -1e30f, v2 = -1e30f; int i1 = 0x7fffffff, i2 = 0x7fffffff;
#pragma unroll
            for (int n8 = 0; n8 < 8; n8++){
                const int c0 = n8*8 + (lane & 3)*2;
                top2_push(v1, i1, v2, i2, acc[mb][n8][h*2+0], c0);
                top2_push(v1, i1, v2, i2, acc[mb][n8][h*2+1], c0+1);
            }
#pragma unroll
            for (int o = 1; o <= 2; o <<= 1){
                const float w1 = __shfl_xor_sync(0xffffffffu, v1, o);
                const int   j1 = __shfl_xor_sync(0xffffffffu, i1, o);
                const float w2 = __shfl_xor_sync(0xffffffffu, v2, o);
                const int   j2 = __shfl_xor_sync(0xffffffffu, i2, o);
                top2_push(v1, i1, v2, i2, w1, j1);
                top2_push(v1, i1, v2, i2, w2, j2);
            }
            if ((lane & 3) == 0){
                const int row = warp_m*32 + mb*16 + h*8 + (lane >> 2);
                sval1[row*2 + warp_n] = v1; sidx1[row*2 + warp_n] = warp_n*64 + i1;
                sval2[row*2 + warp_n] = v2; sidx2[row*2 + warp_n] = warp_n*64 + i2;
            }
        }
    __syncthreads();
    if (tid < 128){
        float v1 = sval1[tid*2]; int i1 = sidx1[tid*2];
        float v2 = sval2[tid*2]; int i2 = sidx2[tid*2];
        top2_push(v1, i1, v2, i2, sval1[tid*2+1], sidx1[tid*2+1]);
        top2_push(v1, i1, v2, i2, sval2[tid*2+1], sidx2[tid*2+1]);
        const int grow = mt*128 + tid;
        g_cand_val [grow*NT + nt] = v1;
        g_cand_idx [grow*NT + nt] = nt*BN + i1;
        g_cand_val2[grow*NT + nt] = v2;
        g_cand_idx2[grow*NT + nt] = nt*BN + i2;
    }
}

// ---------------- K2: top-10 tiles x top-2 atoms, exact fp32 rescore + update ----
__global__ void itda_update(const float* __restrict__ x, const float* __restrict__ xsm){
    const int b = blockIdx.x, tid = threadIdx.x;
    __shared__ float sv[256];
    __shared__ int   si[256];
    __shared__ float sred[8];
    __shared__ int   s_cand[2*NTSEL];
    __shared__ int   s_list[34];
    __shared__ float s_w[34];
    __shared__ float s_grad[34];
    __shared__ int   s_n, s_newpos;

    const float4 r4 = ((const float4*)(g_resid + (size_t)b*Dd))[tid];

    // select top-NTSEL tiles by (bf16-approx) tile max; tid indexes the tile
    float cv = g_cand_val[b*NT + tid];
    for (int r = 0; r < NTSEL; r++){
        __syncthreads();
        sv[tid] = cv; si[tid] = tid;
        __syncthreads();
        for (int off = 128; off; off >>= 1){
            if (tid < off){
                const float ov = sv[tid+off]; const int oi = si[tid+off];
                if (ov > sv[tid] || (ov == sv[tid] && oi < si[tid])){ sv[tid]=ov; si[tid]=oi; }
            }
            __syncthreads();
        }
        const int win = si[0];
        if (tid == 0){
            s_cand[2*r+0] = g_cand_idx [b*NT + win];
            s_cand[2*r+1] = g_cand_idx2[b*NT + win];
        }
        if (tid == win) cv = -1e30f;
    }
    __syncthreads();

    // exact fp32 rescore of 2*NTSEL candidates -> argmax (first-index tie rule)
    float best = -1e30f; int bidx = 0x7fffffff;
    for (int r = 0; r < 2*NTSEL; r++){
        const int c = s_cand[r];
        const float4 v = ((const float4*)(xsm + (size_t)c*Dd))[tid];
        const float e = block_sum(r4.x*v.x + r4.y*v.y + r4.z*v.z + r4.w*v.w, sred);
        if (e > best || (e == best && c < bidx)){ best = e; bidx = c; }
    }

    // active list: S = {w>0} U {argmax}
    const int n0 = g_nsel[b];
    if (tid < n0){ s_list[tid] = g_sel_idx[b*34 + tid]; s_w[tid] = g_sel_w[b*34 + tid]; }
    __syncthreads();
    if (tid == 0){
        int pos = -1, n = n0;
        for (int j = 0; j < n; j++) if (s_list[j] == bidx){ pos = j; break; }
        if (pos < 0){ pos = n; s_list[n] = bidx; s_w[n] = 0.f; n++; }
        s_n = n; s_newpos = pos;
    }
    __syncthreads();
    const int n = s_n, newpos = s_newpos;

    // grads (exact IPs on S) + c = grad @ xs fused
    float4 c4 = make_float4(0.f,0.f,0.f,0.f);
    for (int j = 0; j < n; j++){
        const bool inS = (s_w[j] > 0.f) || (j == newpos);
        if (inS){
            const float4 v = ((const float4*)(xsm + (size_t)s_list[j]*Dd))[tid];
            const float g = block_sum(r4.x*v.x + r4.y*v.y + r4.z*v.z + r4.w*v.w, sred);
            if (tid == 0) s_grad[j] = g;
            c4.x += g*v.x; c4.y += g*v.y; c4.z += g*v.z; c4.w += g*v.w;
        } else {
            if (tid == 0) s_grad[j] = 0.f;
        }
    }
    const float csq  = block_sum(c4.x*c4.x + c4.y*c4.y + c4.z*c4.z + c4.w*c4.w, sred);
    const float cr   = block_sum(c4.x*r4.x + c4.y*r4.y + c4.z*r4.z + c4.w*r4.w, sred);
    const float step = cr / fmaxf(csq, 1e-3f);

    if (tid == 0){
        for (int j = 0; j < n; j++)
            s_w[j] = fmaxf(0.f, s_w[j] + step * s_grad[j]);
    }
    __syncthreads();

    // residual = x - sum_j w_j * xs_j (recomputed exactly)
    float4 xv = ((const float4*)(x + (size_t)b*Dd))[tid];
    for (int j = 0; j < n; j++){
        const float w = s_w[j];
        if (w > 0.f){
            const float4 v = ((const float4*)(xsm + (size_t)s_list[j]*Dd))[tid];
            xv.x -= w*v.x; xv.y -= w*v.y; xv.z -= w*v.z; xv.w -= w*v.w;
        }
    }
    ((float4*)(g_resid + (size_t)b*Dd))[tid] = xv;
    store_resid_bf16(b, tid, xv);

    if (tid == 0) g_nsel[b] = n;
    if (tid < n){ g_sel_idx[b*34 + tid] = s_list[tid]; g_sel_w[b*34 + tid] = s_w[tid]; }
}

// ---------------- K3: top_k ordering, padding, decode, losses ----------------
__global__ void itda_final(const float* __restrict__ xsm, const float* __restrict__ ysm,
                           const float* __restrict__ y,
                           float* __restrict__ wout, float* __restrict__ iout,
                           float* __restrict__ xr, float* __restrict__ yr,
                           float* __restrict__ ls){
    const int b = blockIdx.x, tid = threadIdx.x;
    __shared__ int   pi[33];
    __shared__ float pw[33];
    __shared__ int   oidx[32];
    __shared__ float ow[32];
    __shared__ int   s_np;
    __shared__ float sred[8];

    if (tid == 0){
        const int nl = g_nsel[b];
        int np = 0;
        for (int j = 0; j < nl; j++){
            const float w = g_sel_w[b*34 + j];
            if (w > 0.f){ pi[np] = g_sel_idx[b*34 + j]; pw[np] = w; np++; }
        }
        for (int a = 0; a < np; a++){
            int bst = a;
            for (int c = a+1; c < np; c++)
                if (pw[c] > pw[bst] || (pw[c] == pw[bst] && pi[c] < pi[bst])) bst = c;
            const float tw = pw[a]; pw[a] = pw[bst]; pw[bst] = tw;
            const int   ti = pi[a]; pi[a] = pi[bst]; pi[bst] = ti;
        }
        int f = 0;
        for (int k = 0; k < L0; k++){
            if (k < np){ ow[k] = pw[k]; oidx[k] = pi[k]; }
            else {
                for (;;){
                    bool used = false;
                    for (int q = 0; q < np; q++) if (pi[q] == f){ used = true; break; }
                    if (!used) break;
                    f++;
                }
                oidx[k] = f; ow[k] = 0.f; f++;
            }
        }
        s_np = np;
    }
    __syncthreads();

    if (tid < L0){
        wout[b*L0 + tid] = ow[tid];
        iout[b*L0 + tid] = (float)oidx[tid];
    }
    const int np = s_np;

    float4 ax = make_float4(0.f,0.f,0.f,0.f);
    float4 ay = make_float4(0.f,0.f,0.f,0.f);
    for (int k = 0; k < np; k++){
        const float w = ow[k];
        const size_t off = (size_t)oidx[k]*Dd;
        const float4 vx = ((const float4*)(xsm + off))[tid];
        const float4 vy = ((const float4*)(ysm + off))[tid];
        ax.x += w*vx.x; ax.y += w*vx.y; ax.z += w*vx.z; ax.w += w*vx.w;
        ay.x += w*vy.x; ay.y += w*vy.y; ay.z += w*vy.z; ay.w += w*vy.w;
    }
    ((float4*)(xr + (size_t)b*Dd))[tid] = ax;
    ((float4*)(yr + (size_t)b*Dd))[tid] = ay;

    const float4 yv = ((const float4*)(y + (size_t)b*Dd))[tid];
    const float d0 = ay.x - yv.x, d1 = ay.y - yv.y, d2 = ay.z - yv.z, d3 = ay.w - yv.w;
    const float L = block_sum(d0*d0 + d1*d1 + d2*d2 + d3*d3, sred);
    if (tid == 0) ls[b] = L;
}

// ---------------- entry ----------------
#define GEMM_SMEM (2*2*TILE_B + 256)   // 2 stages x (A 16KB + B 16KB) + align slack

extern "C" void kernel_launch(void* const* d_in, const int* in_sizes, int n_in,
                              void* d_out, int out_size){
    const float* x  = (const float*)d_in[0];
    const float* y  = (const float*)d_in[1];
    const float* xs = (const float*)d_in[2];
    const float* ys = (const float*)d_in[3];

    float* out  = (float*)d_out;
    float* wout = out;                    // [1024, 32]
    float* iout = out + Bsz*L0;           // [1024, 32] indices as float
    float* xr   = iout + Bsz*L0;          // [1024, 1024]
    float* yr   = xr + (size_t)Bsz*Dd;    // [1024, 1024]
    float* ls   = yr + (size_t)Bsz*Dd;    // [1024]

    cudaFuncSetAttribute(itda_gemm_mma, cudaFuncAttributeMaxDynamicSharedMemorySize, GEMM_SMEM);

    conv_xs<<<NT*NCH, 256>>>(xs);
    itda_init<<<Bsz, 256>>>(x);
    for (int it = 0; it < L0; it++){
        itda_gemm_mma<<<dim3(Bsz/128, NT), 256, GEMM_SMEM>>>();
        itda_update<<<Bsz, 256>>>(x, xs);
    }
    itda_final<<<Bsz, 256>>>(xs, ys, y, wout, iout, xr, yr, ls);
}

// round 5
// speedup vs baseline: 5.9388x; 1.1387x over previous
#include <cuda_runtime.h>
#include <cuda_bf16.h>
#include <cstdint>

typedef unsigned long long ull;

#define Bsz 1024
#define Dd  1024
#define Ff  32768
#define L0  32
#define BN  128
#define NT  (Ff/BN)        // 256 column tiles
#define KC  64             // K per chunk
#define NCH (Dd/KC)        // 16 chunks
#define TILE_B 16384       // 128 rows x 64 bf16 = 16KB
#define NTSEL 10           // tiles rescored (2 atoms each)
#define NST 3              // GEMM pipeline stages

// ---------------- persistent device scratch ----------------
__device__ float g_resid[Bsz*Dd];
__device__ __align__(16) ull g_xs_t[(size_t)Ff*Dd/4];   // 64MB bf16 tiled/swizzled dict
__device__ __align__(16) ull g_a_t[(size_t)Bsz*Dd/4];   // 2MB bf16 tiled residual
__device__ float g_cand_val[Bsz*NT];
__device__ int   g_cand_idx[Bsz*NT];
__device__ float g_cand_val2[Bsz*NT];
__device__ int   g_cand_idx2[Bsz*NT];
__device__ int   g_nsel[Bsz];
__device__ int   g_sel_idx[Bsz*34];
__device__ float g_sel_w[Bsz*34];

// ---------------- helpers ----------------
__device__ __forceinline__ uint32_t smem_u32(const void* p){
    uint32_t a; asm("{ .reg .u64 t; cvta.to.shared.u64 t, %1; cvt.u32.u64 %0, t; }"
                    : "=r"(a) : "l"(p)); return a;
}
__device__ __forceinline__ void cp16(uint32_t dst, const void* src){
    asm volatile("cp.async.cg.shared.global [%0], [%1], 16;" :: "r"(dst), "l"(src) : "memory");
}
__device__ __forceinline__ void cp_commit(){ asm volatile("cp.async.commit_group;" ::: "memory"); }
__device__ __forceinline__ void cp_wait1(){ asm volatile("cp.async.wait_group 1;" ::: "memory"); }
__device__ __forceinline__ void cp_wait0(){ asm volatile("cp.async.wait_group 0;" ::: "memory"); }
__device__ __forceinline__ void ldmx4(uint32_t* r, uint32_t addr){
    asm volatile("ldmatrix.sync.aligned.m8n8.x4.shared.b16 {%0,%1,%2,%3}, [%4];"
        : "=r"(r[0]), "=r"(r[1]), "=r"(r[2]), "=r"(r[3]) : "r"(addr));
}
__device__ __forceinline__ void mma16816(float* d, const uint32_t* a, uint32_t b0, uint32_t b1){
    asm volatile("mma.sync.aligned.m16n8k16.row.col.f32.bf16.bf16.f32 "
        "{%0,%1,%2,%3}, {%4,%5,%6,%7}, {%8,%9}, {%0,%1,%2,%3};"
        : "+f"(d[0]), "+f"(d[1]), "+f"(d[2]), "+f"(d[3])
        : "r"(a[0]), "r"(a[1]), "r"(a[2]), "r"(a[3]), "r"(b0), "r"(b1));
}
__device__ __forceinline__ uint32_t swoff(int row, int colb){
    uint32_t o = (uint32_t)(row*128 + colb);
    return o ^ ((o >> 3) & 0x70);
}
__device__ __forceinline__ ull pack4bf(float a, float b, float c, float d){
    __nv_bfloat162 lo = __floats2bfloat162_rn(a, b);
    __nv_bfloat162 hi = __floats2bfloat162_rn(c, d);
    uint32_t ulo = *reinterpret_cast<uint32_t*>(&lo);
    uint32_t uhi = *reinterpret_cast<uint32_t*>(&hi);
    return (ull)ulo | ((ull)uhi << 32);
}
__device__ __forceinline__ void store_resid_bf16(int b, int tid, float4 v){
    const int m_tile = b >> 7, row = b & 127;
    const int kc = tid >> 4, cg = tid & 15;
    char* dst = (char*)g_a_t + (size_t)(m_tile*NCH + kc)*TILE_B;
    *(ull*)(dst + swoff(row, cg*8)) = pack4bf(v.x, v.y, v.z, v.w);
}
__device__ __forceinline__ float block_sum(float v, float* s){
    const int lane = threadIdx.x & 31, w = threadIdx.x >> 5;
#pragma unroll
    for (int o = 16; o; o >>= 1) v += __shfl_xor_sync(0xffffffffu, v, o);
    __syncthreads();
    if (lane == 0) s[w] = v;
    __syncthreads();
    float r = 0.f;
#pragma unroll
    for (int i = 0; i < 8; i++) r += s[i];
    return r;
}
__device__ __forceinline__ bool better(float a, int ai, float b, int bi){
    return (a > b) || (a == b && ai < bi);
}
__device__ __forceinline__ void top2_push(float &v1, int &i1, float &v2, int &i2, float w, int j){
    if (better(w, j, v1, i1)){ v2 = v1; i2 = i1; v1 = w; i1 = j; }
    else if (better(w, j, v2, i2)){ v2 = w; i2 = j; }
}
// warp-parallel exact fp32 dot: atom (gmem) . residual (smem), 1024 dims
__device__ __forceinline__ float warp_dot(const float* __restrict__ atom,
                                          const float* __restrict__ s_resid, int lane){
    const float4* av = (const float4*)atom;
    const float4* rv = (const float4*)s_resid;
    float s = 0.f;
#pragma unroll
    for (int q = 0; q < 8; q++){
        const float4 a = av[lane + q*32];
        const float4 r = rv[lane + q*32];
        s += a.x*r.x + a.y*r.y + a.z*r.z + a.w*r.w;
    }
#pragma unroll
    for (int o = 16; o; o >>= 1) s += __shfl_xor_sync(0xffffffffu, s, o);
    return s;
}

// ---------------- K-1: dictionary -> tiled/swizzled bf16 ----------------
__global__ void conv_xs(const float* __restrict__ xs){
    const int tile = blockIdx.x;
    const int n_tile = tile >> 4, kc = tile & 15;
    char* dst = (char*)g_xs_t + (size_t)tile*TILE_B;
    for (int g = threadIdx.x; g < 2048; g += 256){
        const int row = g >> 4, cg = g & 15;
        const float4 v = *(const float4*)(xs + (size_t)(n_tile*128 + row)*Dd + kc*KC + cg*4);
        *(ull*)(dst + swoff(row, cg*8)) = pack4bf(v.x, v.y, v.z, v.w);
    }
}

// ---------------- K0: residual = x ----------------
__global__ void itda_init(const float* __restrict__ x){
    const int b = blockIdx.x;
    const float4 v = ((const float4*)(x + (size_t)b*Dd))[threadIdx.x];
    ((float4*)(g_resid + (size_t)b*Dd))[threadIdx.x] = v;
    store_resid_bf16(b, threadIdx.x, v);
    if (threadIdx.x == 0) g_nsel[b] = 0;
}

// ---------------- K1: bf16 HMMA GEMM (3-stage pipeline) + top-2 epilogue -------
__global__ void __launch_bounds__(256, 2) itda_gemm_mma(){
    extern __shared__ __align__(16) char smem_raw[];
    uint32_t sb = (smem_u32(smem_raw) + 127u) & ~127u;
    const int tid = threadIdx.x, wid = tid >> 5, lane = tid & 31;
    const int mt = blockIdx.x, nt = blockIdx.y;
    const int warp_m = wid & 3, warp_n = wid >> 2;

    const char* gA = (const char*)g_a_t  + (size_t)mt*NCH*TILE_B;
    const char* gB = (const char*)g_xs_t + (size_t)nt*NCH*TILE_B;

    float acc[2][8][4];
#pragma unroll
    for (int i = 0; i < 2; i++)
#pragma unroll
        for (int j = 0; j < 8; j++)
#pragma unroll
            for (int q = 0; q < 4; q++) acc[i][j][q] = 0.f;

    const int lrow = ((lane >> 3) & 1)*8 + (lane & 7);
    const int lkb  = (lane >> 4)*16;
    const int rA0 = warp_m*32 + lrow;
    const int rB0 = warp_n*64 + lrow;

    auto issue = [&](int c, int s){
        const uint32_t dA = sb + s*32768 + tid*16;
        const uint32_t dB = dA + 16384;
        const char* srcA = gA + (size_t)c*TILE_B + tid*16;
        const char* srcB = gB + (size_t)c*TILE_B + tid*16;
#pragma unroll
        for (int i = 0; i < 4; i++){
            cp16(dA + i*4096, srcA + i*4096);
            cp16(dB + i*4096, srcB + i*4096);
        }
        cp_commit();
    };

    issue(0, 0);
    issue(1, 1);
    for (int c = 0; c < NCH; c++){
        const int s = c % NST;
        if (c + 1 < NCH) cp_wait1(); else cp_wait0();
        __syncthreads();
        if (c + 2 < NCH) issue(c + 2, (c + 2) % NST);
        const uint32_t sA = sb + s*32768;
        const uint32_t sB = sA + 16384;
#pragma unroll
        for (int ks = 0; ks < 4; ks++){
            const int kb = ks*32 + lkb;
            uint32_t a[2][4];
            ldmx4(a[0], sA + swoff(rA0,      kb));
            ldmx4(a[1], sA + swoff(rA0 + 16, kb));
            uint32_t b[4][4];
#pragma unroll
            for (int nb = 0; nb < 4; nb++)
                ldmx4(b[nb], sB + swoff(rB0 + nb*16, kb));
#pragma unroll
            for (int mb = 0; mb < 2; mb++)
#pragma unroll
                for (int n8 = 0; n8 < 8; n8++){
                    const int nb = n8 >> 1, t = n8 & 1;
                    mma16816(acc[mb][n8], a[mb], b[nb][t], b[nb][2+t]);
                }
        }
    }
    __syncthreads();    // all compute done before epilogue reuses stage-0 smem

    // epilogue: per-row TOP-2 (val, first-idx) over this 128-col tile
    float* sval1 = (float*)smem_raw;             // [128][2]
    int*   sidx1 = (int*)(smem_raw + 1024);
    float* sval2 = (float*)(smem_raw + 2048);
    int*   sidx2 = (int*)(smem_raw + 3072);
#pragma unroll
    for (int mb = 0; mb < 2; mb++)
#pragma unroll
        for (int h = 0; h < 2; h++){
            float v1 = -1e30f, v2 = -1e30f; int i1 = 0x7fffffff, i2 = 0x7fffffff;
#pragma unroll
            for (int n8 = 0; n8 < 8; n8++){
                const int c0 = n8*8 + (lane & 3)*2;
                top2_push(v1, i1, v2, i2, acc[mb][n8][h*2+0], c0);
                top2_push(v1, i1, v2, i2, acc[mb][n8][h*2+1], c0+1);
            }
#pragma unroll
            for (int o = 1; o <= 2; o <<= 1){
                const float w1 = __shfl_xor_sync(0xffffffffu, v1, o);
                const int   j1 = __shfl_xor_sync(0xffffffffu, i1, o);
                const float w2 = __shfl_xor_sync(0xffffffffu, v2, o);
                const int   j2 = __shfl_xor_sync(0xffffffffu, i2, o);
                top2_push(v1, i1, v2, i2, w1, j1);
                top2_push(v1, i1, v2, i2, w2, j2);
            }
            if ((lane & 3) == 0){
                const int row = warp_m*32 + mb*16 + h*8 + (lane >> 2);
                sval1[row*2 + warp_n] = v1; sidx1[row*2 + warp_n] = warp_n*64 + i1;
                sval2[row*2 + warp_n] = v2; sidx2[row*2 + warp_n] = warp_n*64 + i2;
            }
        }
    __syncthreads();
    if (tid < 128){
        float v1 = sval1[tid*2]; int i1 = sidx1[tid*2];
        float v2 = sval2[tid*2]; int i2 = sidx2[tid*2];
        top2_push(v1, i1, v2, i2, sval1[tid*2+1], sidx1[tid*2+1]);
        top2_push(v1, i1, v2, i2, sval2[tid*2+1], sidx2[tid*2+1]);
        const int grow = mt*128 + tid;
        g_cand_val [grow*NT + nt] = v1;
        g_cand_idx [grow*NT + nt] = nt*BN + i1;
        g_cand_val2[grow*NT + nt] = v2;
        g_cand_idx2[grow*NT + nt] = nt*BN + i2;
    }
}

// ---------------- K2: warp-parallel rescore/grads + incremental residual -------
__global__ void itda_update(const float* __restrict__ xsm){
    const int b = blockIdx.x, tid = threadIdx.x;
    const int wid = tid >> 5, lane = tid & 31;
    __shared__ __align__(16) float s_resid[Dd];
    __shared__ float sred[8];
    __shared__ float s_tv[8];
    __shared__ int   s_ti[8];
    __shared__ int   s_wt[NTSEL];
    __shared__ int   s_win;
    __shared__ int   s_cand[2*NTSEL];
    __shared__ float s_dot[2*NTSEL];
    __shared__ int   s_list[34];
    __shared__ float s_w[34];
    __shared__ float s_grad[34];
    __shared__ int   s_n, s_newpos, s_bidx;
    __shared__ float s_bval;
    __shared__ int   s_nclip;
    __shared__ int   s_clip[34];
    __shared__ float s_cw[34];

    // stage residual in smem (also kept per-thread as r4 for the update)
    const float4 r4 = ((const float4*)(g_resid + (size_t)b*Dd))[tid];
    ((float4*)s_resid)[tid] = r4;
    if (tid == 0) s_nclip = 0;

    // --- select top-NTSEL tiles by bf16 tile max (2 barriers/round) ---
    float cv = g_cand_val[b*NT + tid];
    for (int r = 0; r < NTSEL; r++){
        float v = cv; int t = tid;
#pragma unroll
        for (int o = 16; o; o >>= 1){
            const float ov = __shfl_xor_sync(0xffffffffu, v, o);
            const int   ot = __shfl_xor_sync(0xffffffffu, t, o);
            if (better(ov, ot, v, t)){ v = ov; t = ot; }
        }
        if (lane == 0){ s_tv[wid] = v; s_ti[wid] = t; }
        __syncthreads();
        if (tid == 0){
            float bv = s_tv[0]; int bt = s_ti[0];
#pragma unroll
            for (int i = 1; i < 8; i++)
                if (better(s_tv[i], s_ti[i], bv, bt)){ bv = s_tv[i]; bt = s_ti[i]; }
            s_wt[r] = bt; s_win = bt;
        }
        __syncthreads();
        if (tid == s_win) cv = -1e30f;
    }
    if (tid < NTSEL){
        const int w = s_wt[tid];
        s_cand[2*tid+0] = g_cand_idx [b*NT + w];
        s_cand[2*tid+1] = g_cand_idx2[b*NT + w];
    }
    __syncthreads();

    // --- exact fp32 rescore, warp-per-candidate ---
#pragma unroll
    for (int r = 0; r < (2*NTSEL + 7)/8; r++){
        const int k = wid + r*8;
        if (k < 2*NTSEL){
            const float d = warp_dot(xsm + (size_t)s_cand[k]*Dd, s_resid, lane);
            if (lane == 0) s_dot[k] = d;
        }
    }
    __syncthreads();
    if (wid == 0){
        float v = (lane < 2*NTSEL) ? s_dot[lane] : -1e30f;
        int   i = (lane < 2*NTSEL) ? s_cand[lane] : 0x7fffffff;
#pragma unroll
        for (int o = 16; o; o >>= 1){
            const float ov = __shfl_xor_sync(0xffffffffu, v, o);
            const int   oi = __shfl_xor_sync(0xffffffffu, i, o);
            if (better(ov, oi, v, i)){ v = ov; i = oi; }
        }
        if (lane == 0){ s_bidx = i; s_bval = v; }
    }
    __syncthreads();
    const int bidx = s_bidx;

    // --- active list: S = {w>0} U {argmax} ---
    const int n0 = g_nsel[b];
    if (tid < n0){ s_list[tid] = g_sel_idx[b*34 + tid]; s_w[tid] = g_sel_w[b*34 + tid]; }
    __syncthreads();
    if (tid == 0){
        int pos = -1, n = n0;
        for (int j = 0; j < n; j++) if (s_list[j] == bidx){ pos = j; break; }
        if (pos < 0){ pos = n; s_list[n] = bidx; s_w[n] = 0.f; n++; }
        s_n = n; s_newpos = pos;
    }
    __syncthreads();
    const int n = s_n, newpos = s_newpos;

    // --- grads, warp-per-atom (newpos reuses rescore value) ---
    for (int r = 0; r < (n + 7) >> 3; r++){
        const int j = wid + r*8;
        if (j < n){
            if (j == newpos){
                if (lane == 0) s_grad[j] = s_bval;
            } else if (s_w[j] > 0.f){
                const float g = warp_dot(xsm + (size_t)s_list[j]*Dd, s_resid, lane);
                if (lane == 0) s_grad[j] = g;
            } else if (lane == 0) s_grad[j] = 0.f;
        }
    }
    __syncthreads();

    // --- c = grad @ xs (per-thread 4-dim slice) ---
    float4 c4 = make_float4(0.f,0.f,0.f,0.f);
    for (int j = 0; j < n; j++){
        const float g = s_grad[j];
        if (g != 0.f){
            const float4 v = ((const float4*)(xsm + (size_t)s_list[j]*Dd))[tid];
            c4.x += g*v.x; c4.y += g*v.y; c4.z += g*v.z; c4.w += g*v.w;
        }
    }
    const float csq  = block_sum(c4.x*c4.x + c4.y*c4.y + c4.z*c4.z + c4.w*c4.w, sred);
    const float cr   = block_sum(c4.x*r4.x + c4.y*r4.y + c4.z*r4.z + c4.w*r4.w, sred);
    const float step = cr / fmaxf(csq, 1e-3f);

    // --- weight update + clip detection ---
    if (tid < n){
        const float g  = s_grad[tid];
        const float wn = s_w[tid] + step * g;
        s_w[tid] = fmaxf(wn, 0.f);
        if (g != 0.f && wn < 0.f){
            const int p = atomicAdd(&s_nclip, 1);
            s_clip[p] = tid; s_cw[p] = wn;          // negative value
        }
    }
    __syncthreads();

    // --- incremental residual: r' = r - step*c + sum_clipped (w+s*g)*v ---
    float4 xv;
    xv.x = r4.x - step*c4.x; xv.y = r4.y - step*c4.y;
    xv.z = r4.z - step*c4.z; xv.w = r4.w - step*c4.w;
    const int nclip = s_nclip;
    for (int q = 0; q < nclip; q++){
        const float wneg = s_cw[q];
        const float4 v = ((const float4*)(xsm + (size_t)s_list[s_clip[q]]*Dd))[tid];
        xv.x += wneg*v.x; xv.y += wneg*v.y; xv.z += wneg*v.z; xv.w += wneg*v.w;
    }
    ((float4*)(g_resid + (size_t)b*Dd))[tid] = xv;
    store_resid_bf16(b, tid, xv);

    if (tid == 0) g_nsel[b] = n;
    if (tid < n){ g_sel_idx[b*34 + tid] = s_list[tid]; g_sel_w[b*34 + tid] = s_w[tid]; }
}

// ---------------- K3: top_k ordering, padding, decode, losses ----------------
__global__ void itda_final(const float* __restrict__ xsm, const float* __restrict__ ysm,
                           const float* __restrict__ y,
                           float* __restrict__ wout, float* __restrict__ iout,
                           float* __restrict__ xr, float* __restrict__ yr,
                           float* __restrict__ ls){
    const int b = blockIdx.x, tid = threadIdx.x;
    __shared__ int   pi[33];
    __shared__ float pw[33];
    __shared__ int   oidx[32];
    __shared__ float ow[32];
    __shared__ int   s_np;
    __shared__ float sred[8];

    if (tid == 0){
        const int nl = g_nsel[b];
        int np = 0;
        for (int j = 0; j < nl; j++){
            const float w = g_sel_w[b*34 + j];
            if (w > 0.f){ pi[np] = g_sel_idx[b*34 + j]; pw[np] = w; np++; }
        }
        for (int a = 0; a < np; a++){
            int bst = a;
            for (int c = a+1; c < np; c++)
                if (pw[c] > pw[bst] || (pw[c] == pw[bst] && pi[c] < pi[bst])) bst = c;
            const float tw = pw[a]; pw[a] = pw[bst]; pw[bst] = tw;
            const int   ti = pi[a]; pi[a] = pi[bst]; pi[bst] = ti;
        }
        int f = 0;
        for (int k = 0; k < L0; k++){
            if (k < np){ ow[k] = pw[k]; oidx[k] = pi[k]; }
            else {
                for (;;){
                    bool used = false;
                    for (int q = 0; q < np; q++) if (pi[q] == f){ used = true; break; }
                    if (!used) break;
                    f++;
                }
                oidx[k] = f; ow[k] = 0.f; f++;
            }
        }
        s_np = np;
    }
    __syncthreads();

    if (tid < L0){
        wout[b*L0 + tid] = ow[tid];
        iout[b*L0 + tid] = (float)oidx[tid];
    }
    const int np = s_np;

    float4 ax = make_float4(0.f,0.f,0.f,0.f);
    float4 ay = make_float4(0.f,0.f,0.f,0.f);
    for (int k = 0; k < np; k++){
        const float w = ow[k];
        const size_t off = (size_t)oidx[k]*Dd;
        const float4 vx = ((const float4*)(xsm + off))[tid];
        const float4 vy = ((const float4*)(ysm + off))[tid];
        ax.x += w*vx.x; ax.y += w*vx.y; ax.z += w*vx.z; ax.w += w*vx.w;
        ay.x += w*vy.x; ay.y += w*vy.y; ay.z += w*vy.z; ay.w += w*vy.w;
    }
    ((float4*)(xr + (size_t)b*Dd))[tid] = ax;
    ((float4*)(yr + (size_t)b*Dd))[tid] = ay;

    const float4 yv = ((const float4*)(y + (size_t)b*Dd))[tid];
    const float d0 = ay.x - yv.x, d1 = ay.y - yv.y, d2 = ay.z - yv.z, d3 = ay.w - yv.w;
    const float L = block_sum(d0*d0 + d1*d1 + d2*d2 + d3*d3, sred);
    if (tid == 0) ls[b] = L;
}

// ---------------- entry ----------------
#define GEMM_SMEM (NST*2*TILE_B + 256)   // 3 stages x (A 16KB + B 16KB) + align slack

extern "C" void kernel_launch(void* const* d_in, const int* in_sizes, int n_in,
                              void* d_out, int out_size){
    const float* x  = (const float*)d_in[0];
    const float* y  = (const float*)d_in[1];
    const float* xs = (const float*)d_in[2];
    const float* ys = (const float*)d_in[3];

    float* out  = (float*)d_out;
    float* wout = out;                    // [1024, 32]
    float* iout = out + Bsz*L0;           // [1024, 32] indices as float
    float* xr   = iout + Bsz*L0;          // [1024, 1024]
    float* yr   = xr + (size_t)Bsz*Dd;    // [1024, 1024]
    float* ls   = yr + (size_t)Bsz*Dd;    // [1024]

    cudaFuncSetAttribute(itda_gemm_mma, cudaFuncAttributeMaxDynamicSharedMemorySize, GEMM_SMEM);

    conv_xs<<<NT*NCH, 256>>>(xs);
    itda_init<<<Bsz, 256>>>(x);
    for (int it = 0; it < L0; it++){
        itda_gemm_mma<<<dim3(Bsz/128, NT), 256, GEMM_SMEM>>>();
        itda_update<<<Bsz, 256>>>(xs);
    }
    itda_final<<<Bsz, 256>>>(xs, ys, y, wout, iout, xr, yr, ls);
}